// round 2
// baseline (speedup 1.0000x reference)
#include <cuda_runtime.h>
#include <cstdint>

typedef unsigned long long ULL;

__device__ __forceinline__ ULL pack2(float lo, float hi) {
    ULL r; asm("mov.b64 %0, {%1, %2};" : "=l"(r) : "f"(lo), "f"(hi)); return r;
}
__device__ __forceinline__ void unpack2(ULL v, float& lo, float& hi) {
    asm("mov.b64 {%0, %1}, %2;" : "=f"(lo), "=f"(hi) : "l"(v));
}
__device__ __forceinline__ ULL fma2(ULL a, ULL b, ULL c) {
    ULL d; asm("fma.rn.f32x2 %0, %1, %2, %3;" : "=l"(d) : "l"(a), "l"(b), "l"(c)); return d;
}

#define NN 256
#define HH 64

// scratch: Hsum[node = b*256+j][64]
__device__ float g_Hs[4 * 256 * 64];

// ============================================================================
// K1: one block per (b,j). Hsum[bx][0..63] = sum_i relu(e[b,i,j,:]@W1 + b1)
// ============================================================================
__global__ __launch_bounds__(128, 7)
void k_edge(const float* __restrict__ edge,
            const float* __restrict__ W1,
            const float* __restrict__ b1) {
    __shared__ float es[64 * 10];   // 64 i-rows/chunk, pitch 10 (8 used)
    __shared__ float w1s[512];
    __shared__ float hsum[64];

    const int t  = threadIdx.x;
    const int bx = blockIdx.x;       // node id
    const int j  = bx & 255;
    const int b  = bx >> 8;

    if (t < 64) hsum[t] = 0.f;
    w1s[t]       = W1[t];
    w1s[t + 128] = W1[t + 128];
    w1s[t + 256] = W1[t + 256];
    w1s[t + 384] = W1[t + 384];
    __syncthreads();

    const int ii = t >> 4;           // 8 i-groups
    const int kg = t & 15;           // 16 neuron groups of 4
    const int k0 = kg * 4;

    ULL w12[4][4], b1i[4];
    #pragma unroll
    for (int kk = 0; kk < 4; kk++) {
        b1i[kk] = pack2(b1[k0 + kk], 0.f);
        #pragma unroll
        for (int g = 0; g < 4; g++)
            w12[g][kk] = pack2(w1s[(2 * g) * HH + k0 + kk],
                               w1s[(2 * g + 1) * HH + k0 + kk]);
    }

    float acc[4] = {0.f, 0.f, 0.f, 0.f};

    const int il = t >> 1, q = t & 1;   // loader: row-in-chunk, float4 half
    const float4* src = reinterpret_cast<const float4*>(edge)
                        + ((ULL)(b * NN) * NN + j) * 2 + q;   // +512 per i

    float4 v = src[(ULL)il * 512];

    #pragma unroll 1
    for (int c = 0; c < 4; c++) {
        __syncthreads();
        *(float2*)&es[il * 10 + q * 4]     = make_float2(v.x, v.y);
        *(float2*)&es[il * 10 + q * 4 + 2] = make_float2(v.z, v.w);
        __syncthreads();
        if (c < 3) v = src[(ULL)((c + 1) * 64 + il) * 512];

        #pragma unroll
        for (int s = 0; s < 8; s++) {
            const float* er = &es[(ii * 8 + s) * 10];
            ULL e0 = *(const ULL*)&er[0];
            ULL e1 = *(const ULL*)&er[2];
            ULL e2 = *(const ULL*)&er[4];
            ULL e3 = *(const ULL*)&er[6];
            #pragma unroll
            for (int kk = 0; kk < 4; kk++) {
                ULL h = fma2(e0, w12[0][kk], b1i[kk]);
                h = fma2(e1, w12[1][kk], h);
                h = fma2(e2, w12[2][kk], h);
                h = fma2(e3, w12[3][kk], h);
                float lo, hi; unpack2(h, lo, hi);
                acc[kk] += fmaxf(lo + hi, 0.f);
            }
        }
    }

    #pragma unroll
    for (int kk = 0; kk < 4; kk++) {
        float vs = acc[kk] + __shfl_xor_sync(0xffffffffu, acc[kk], 16);
        if ((t & 16) == 0) atomicAdd(&hsum[k0 + kk], vs);
    }
    __syncthreads();
    if (t < 64) g_Hs[bx * 64 + t] = hsum[t];
}

// ============================================================================
// K2: 8 nodes per block. wsum = Hsum@W2 (two 32-row K-halves of W2 in SMEM),
// then out[n,d] = sum_c x[c]*(wsum[c*16+d] + 256*b2 + root)
// ============================================================================
__global__ __launch_bounds__(128)
void k_node(const float* __restrict__ x,
            const float* __restrict__ W2,
            const float* __restrict__ b2,
            const float* __restrict__ root,
            float* __restrict__ out) {
    __shared__ float w2s[32 * 256];   // 32 KB half of W2
    __shared__ ULL   hs2[8 * 64];     // Hsum splat for FFMA2
    __shared__ float wsum[8 * 256];
    __shared__ float rb[256];
    __shared__ float xs[128];

    const int t     = threadIdx.x;
    const int node0 = blockIdx.x * 8;

    #pragma unroll
    for (int r = 0; r < 4; r++) {
        float hv = g_Hs[node0 * 64 + t * 4 + r];
        hs2[t * 4 + r] = pack2(hv, hv);
    }
    rb[t]       = 256.f * b2[t]       + root[t];
    rb[t + 128] = 256.f * b2[t + 128] + root[t + 128];
    xs[t] = x[node0 * 16 + t];

    const int ng  = t >> 5;          // nodes 2ng, 2ng+1
    const int cd0 = (t & 31) * 8;    // 8 output columns

    ULL acc[2][4];
    #pragma unroll
    for (int n = 0; n < 2; n++)
        #pragma unroll
        for (int p = 0; p < 4; p++) acc[n][p] = pack2(0.f, 0.f);

    #pragma unroll 1
    for (int half = 0; half < 2; half++) {
        __syncthreads();
        const float4* w2g = reinterpret_cast<const float4*>(W2 + half * 32 * 256);
        float4*       w2d = reinterpret_cast<float4*>(w2s);
        #pragma unroll
        for (int r = 0; r < 16; r++) w2d[r * 128 + t] = w2g[r * 128 + t];
        __syncthreads();

        #pragma unroll 4
        for (int k = 0; k < 32; k++) {
            ULL a0 = hs2[(2 * ng)     * 64 + half * 32 + k];
            ULL a1 = hs2[(2 * ng + 1) * 64 + half * 32 + k];
            const float* wr = &w2s[k * 256 + cd0];
            #pragma unroll
            for (int p = 0; p < 4; p++) {
                ULL bv = *(const ULL*)&wr[2 * p];
                acc[0][p] = fma2(a0, bv, acc[0][p]);
                acc[1][p] = fma2(a1, bv, acc[1][p]);
            }
        }
    }

    #pragma unroll
    for (int n = 0; n < 2; n++)
        #pragma unroll
        for (int p = 0; p < 4; p++)
            *(ULL*)&wsum[(2 * ng + n) * 256 + cd0 + 2 * p] = acc[n][p];
    __syncthreads();

    const int n = t >> 4, d = t & 15;
    float o = 0.f;
    #pragma unroll
    for (int c = 0; c < 16; c++)
        o += xs[n * 16 + c] * (wsum[n * 256 + c * 16 + d] + rb[c * 16 + d]);
    out[(node0 + n) * 16 + d] = o;
}

extern "C" void kernel_launch(void* const* d_in, const int* in_sizes, int n_in,
                              void* d_out, int out_size) {
    const float* node_attr = (const float*)d_in[0];
    const float* edge_adj  = (const float*)d_in[1];
    const float* W1        = (const float*)d_in[2];
    const float* b1        = (const float*)d_in[3];
    const float* W2        = (const float*)d_in[4];
    const float* b2        = (const float*)d_in[5];
    const float* root      = (const float*)d_in[6];
    float* out = (float*)d_out;

    k_edge<<<1024, 128>>>(edge_adj, W1, b1);
    k_node<<<128, 128>>>(node_attr, W2, b2, root, out);
}